// round 3
// baseline (speedup 1.0000x reference)
#include <cuda_runtime.h>
#include <cuda_bf16.h>
#include <cstdint>

// ---------------------------------------------------------------------------
// RGCN (2 layers), transform-first formulation:
//   Y1[n, r*256+g] = sum_f x[n,f] * W1[r,f,g]           (8 GEMMs, N x 256 x 256)
//   Hpre = x @ root1 + b1                               (GEMM)
//   Hpre[dst] += (1/deg(dst,rel)) * Y1[src, rel,:]      (edge scatter, REDG)
//   H = relu(Hpre)
//   Y2[n, r*128+g] = sum_f H[n,f] * W2[r,f,g]
//   out = H @ root2 + b2 ; out[dst] += norm * Y2[src, rel,:]
// Edge indices arrive as int32 (harness dtype set: f32/i32/bf16).
// ---------------------------------------------------------------------------

#define MAXN 50000
#define RELS 8

__device__ float g_Y1[(size_t)MAXN * 2048];   // 409.6 MB
__device__ float g_H [(size_t)MAXN * 256];    // 51.2 MB
__device__ float g_Y2[(size_t)MAXN * 1024];   // 204.8 MB
__device__ int   g_cnt[MAXN * RELS];

// ---------------------------------------------------------------------------
// fp32 tiled GEMM:  C[M, *] = A[M,256] @ B[256, ncols(B)=ldb] (+ bias)
// BM=128, BN=128, BK=16, 256 threads, 8x8 per thread.
// ---------------------------------------------------------------------------
__global__ void __launch_bounds__(256)
gemm256(const float* __restrict__ A, const float* __restrict__ B,
        const float* __restrict__ bias, float* __restrict__ C,
        int M, int ldb, int ldc, int col_off)
{
    __shared__ float As[16][128 + 4];
    __shared__ float Bs[16][128 + 4];

    const int tid = threadIdx.x;
    const int bm = blockIdx.x * 128;
    const int bn = blockIdx.y * 128;      // column within B

    const int a_row = tid >> 2;           // 0..63
    const int a_k4  = (tid & 3) * 4;      // 0,4,8,12
    const int b_row = tid >> 5;           // 0..7
    const int b_c4  = (tid & 31) * 4;     // 0..124

    const int tx = tid & 15;
    const int ty = tid >> 4;

    float acc[8][8];
#pragma unroll
    for (int i = 0; i < 8; i++)
#pragma unroll
        for (int j = 0; j < 8; j++) acc[i][j] = 0.f;

    for (int k0 = 0; k0 < 256; k0 += 16) {
        // load A tile (transposed into As[k][row])
#pragma unroll
        for (int h = 0; h < 2; h++) {
            int r  = a_row + h * 64;
            int gr = bm + r;
            float4 v = make_float4(0.f, 0.f, 0.f, 0.f);
            if (gr < M) v = *(const float4*)(A + (size_t)gr * 256 + k0 + a_k4);
            As[a_k4 + 0][r] = v.x;
            As[a_k4 + 1][r] = v.y;
            As[a_k4 + 2][r] = v.z;
            As[a_k4 + 3][r] = v.w;
        }
        // load B tile
#pragma unroll
        for (int h = 0; h < 2; h++) {
            int kr = b_row + h * 8;
            float4 v = *(const float4*)(B + (size_t)(k0 + kr) * ldb + bn + b_c4);
            *(float4*)&Bs[kr][b_c4] = v;
        }
        __syncthreads();

#pragma unroll
        for (int k = 0; k < 16; k++) {
            float4 a0 = *(const float4*)&As[k][ty * 8];
            float4 a1 = *(const float4*)&As[k][ty * 8 + 4];
            float4 b0 = *(const float4*)&Bs[k][tx * 8];
            float4 b1 = *(const float4*)&Bs[k][tx * 8 + 4];
            float a[8] = {a0.x, a0.y, a0.z, a0.w, a1.x, a1.y, a1.z, a1.w};
            float b[8] = {b0.x, b0.y, b0.z, b0.w, b1.x, b1.y, b1.z, b1.w};
#pragma unroll
            for (int i = 0; i < 8; i++)
#pragma unroll
                for (int j = 0; j < 8; j++)
                    acc[i][j] += a[i] * b[j];
        }
        __syncthreads();
    }

    float bv[8];
#pragma unroll
    for (int j = 0; j < 8; j++)
        bv[j] = bias ? bias[bn + tx * 8 + j] : 0.f;

#pragma unroll
    for (int i = 0; i < 8; i++) {
        int gr = bm + ty * 8 + i;
        if (gr < M) {
            float* crow = C + (size_t)gr * ldc + col_off + bn + tx * 8;
#pragma unroll
            for (int j = 0; j < 8; j += 4) {
                float4 v = make_float4(acc[i][j] + bv[j], acc[i][j + 1] + bv[j + 1],
                                       acc[i][j + 2] + bv[j + 2], acc[i][j + 3] + bv[j + 3]);
                *(float4*)(crow + j) = v;
            }
        }
    }
}

// ---------------------------------------------------------------------------
// Edge kernels (int32 indices)
// ---------------------------------------------------------------------------
__global__ void zero_int_kernel(int* p, int n)
{
    int i = blockIdx.x * blockDim.x + threadIdx.x;
    if (i < n) p[i] = 0;
}

__global__ void count_kernel(const int* __restrict__ ei,
                             const int* __restrict__ et,
                             int* __restrict__ cnt, int E)
{
    int e = blockIdx.x * blockDim.x + threadIdx.x;
    if (e < E) {
        int dst = ei[E + e];
        int rel = et[e];
        atomicAdd(&cnt[dst * RELS + rel], 1);
    }
}

// one warp per edge; F = 256 or 128 (F/4 <= 64)
__global__ void __launch_bounds__(256)
scatter_kernel(const float* __restrict__ Y,
               const int* __restrict__ ei,
               const int* __restrict__ et,
               const int* __restrict__ cnt,
               float* __restrict__ out,
               int E, int ldY, int F)
{
    int warp = (blockIdx.x * blockDim.x + threadIdx.x) >> 5;
    int lane = threadIdx.x & 31;
    if (warp >= E) return;

    int src = ei[warp];
    int dst = ei[E + warp];
    int rel = et[warp];
    int deg = cnt[dst * RELS + rel];
    float norm = 1.0f / (float)max(deg, 1);

    const float4* yr = (const float4*)(Y + (size_t)src * ldY + rel * F);
    float* orow = out + (size_t)dst * F;

    int nq = F >> 2;
    for (int i = lane; i < nq; i += 32) {
        float4 v = __ldg(&yr[i]);
        float* p = orow + i * 4;
        atomicAdd(p + 0, v.x * norm);
        atomicAdd(p + 1, v.y * norm);
        atomicAdd(p + 2, v.z * norm);
        atomicAdd(p + 3, v.w * norm);
    }
}

__global__ void relu4_kernel(float* p, size_t n4)
{
    size_t i = (size_t)blockIdx.x * blockDim.x + threadIdx.x;
    if (i < n4) {
        float4 v = ((float4*)p)[i];
        v.x = fmaxf(v.x, 0.f); v.y = fmaxf(v.y, 0.f);
        v.z = fmaxf(v.z, 0.f); v.w = fmaxf(v.w, 0.f);
        ((float4*)p)[i] = v;
    }
}

// ---------------------------------------------------------------------------
extern "C" void kernel_launch(void* const* d_in, const int* in_sizes, int n_in,
                              void* d_out, int out_size)
{
    const float* x     = (const float*)d_in[0];
    const int*   ei    = (const int*)d_in[1];
    const int*   et    = (const int*)d_in[2];
    const float* W1    = (const float*)d_in[3];   // [8,256,256]
    const float* root1 = (const float*)d_in[4];   // [256,256]
    const float* b1    = (const float*)d_in[5];   // [256]
    const float* W2    = (const float*)d_in[6];   // [8,256,128]
    const float* root2 = (const float*)d_in[7];   // [256,128]
    const float* b2    = (const float*)d_in[8];   // [128]
    float*       out   = (float*)d_out;

    const int N = in_sizes[0] / 256;   // 50000
    const int E = in_sizes[2];         // 800000

    float* Y1;  cudaGetSymbolAddress((void**)&Y1, g_Y1);
    float* H;   cudaGetSymbolAddress((void**)&H,  g_H);
    float* Y2;  cudaGetSymbolAddress((void**)&Y2, g_Y2);
    int*   cnt; cudaGetSymbolAddress((void**)&cnt, g_cnt);

    // degree counts
    zero_int_kernel<<<(N * RELS + 255) / 256, 256>>>(cnt, N * RELS);
    count_kernel<<<(E + 255) / 256, 256>>>(ei, et, cnt, E);

    const int mblocks = (N + 127) / 128;

    // ---- layer 1 ----
    {
        dim3 g(mblocks, 2);
        for (int r = 0; r < RELS; r++)
            gemm256<<<g, 256>>>(x, W1 + (size_t)r * 256 * 256, nullptr,
                                Y1, N, 256, 2048, r * 256);
        gemm256<<<g, 256>>>(x, root1, b1, H, N, 256, 256, 0);
    }
    scatter_kernel<<<(E + 7) / 8, 256>>>(Y1, ei, et, cnt, H, E, 2048, 256);
    relu4_kernel<<<(int)(((size_t)N * 64 + 255) / 256), 256>>>(H, (size_t)N * 64);

    // ---- layer 2 ----
    {
        dim3 g(mblocks, 1);
        for (int r = 0; r < RELS; r++)
            gemm256<<<g, 256>>>(H, W2 + (size_t)r * 256 * 128, nullptr,
                                Y2, N, 128, 1024, r * 128);
        gemm256<<<g, 256>>>(H, root2, b2, out, N, 128, 128, 0);
    }
    scatter_kernel<<<(E + 7) / 8, 256>>>(Y2, ei, et, cnt, out, E, 1024, 128);
}

// round 5
// speedup vs baseline: 1.9712x; 1.9712x over previous
#include <cuda_runtime.h>
#include <cuda_bf16.h>
#include <cstdint>

// ============================================================================
// RGCN 2-layer, transform-first. GEMMs via warp-level mma.sync (bf16 2-way
// split: hi*hi + hi*lo + lo*hi, fp32 accum). tcgen05 is unavailable (harness
// builds PTX for compute_103 without the 'a' feature set).
// ============================================================================

#define MAXN 50000
#define RELS 8

__device__ float g_Y1[(size_t)MAXN * 2048];
__device__ float g_H [(size_t)MAXN * 256];
__device__ float g_Y2[(size_t)MAXN * 1024];
__device__ int   g_cnt[MAXN * RELS];

__device__ __nv_bfloat16 g_xh[(size_t)MAXN * 256];
__device__ __nv_bfloat16 g_xl[(size_t)MAXN * 256];
__device__ __nv_bfloat16 g_hh[(size_t)MAXN * 256];
__device__ __nv_bfloat16 g_hl[(size_t)MAXN * 256];

// weights pre-transposed+split: [t = r*ncpr + n][k 0..255]
__device__ __nv_bfloat16 g_w1h[8 * 256 * 256], g_w1l[8 * 256 * 256];
__device__ __nv_bfloat16 g_r1h[256 * 256],     g_r1l[256 * 256];
__device__ __nv_bfloat16 g_w2h[8 * 128 * 256], g_w2l[8 * 128 * 256];
__device__ __nv_bfloat16 g_r2h[128 * 256],     g_r2l[128 * 256];

// ---------------------------------------------------------------------------
__device__ __forceinline__ void ldsm4(uint32_t* r, uint32_t addr)
{
    asm volatile("ldmatrix.sync.aligned.m8n8.x4.shared.b16 {%0,%1,%2,%3}, [%4];"
                 : "=r"(r[0]), "=r"(r[1]), "=r"(r[2]), "=r"(r[3]) : "r"(addr));
}

__device__ __forceinline__ void mma_bf16(float* c, const uint32_t* a, const uint32_t* b)
{
    asm volatile(
        "mma.sync.aligned.m16n8k16.row.col.f32.bf16.bf16.f32 "
        "{%0,%1,%2,%3}, {%4,%5,%6,%7}, {%8,%9}, {%0,%1,%2,%3};"
        : "+f"(c[0]), "+f"(c[1]), "+f"(c[2]), "+f"(c[3])
        : "r"(a[0]), "r"(a[1]), "r"(a[2]), "r"(a[3]), "r"(b[0]), "r"(b[1]));
}

// ---------------------------------------------------------------------------
// GEMM: C[M, T] = A[M,256] @ Bt[T,256]^T (+bias). A,Bt given as bf16 hi/lo.
// CTA: 128x128 tile. 8 warps: 2x4 grid of 64x32 warp tiles. kc=32.
// smem rows padded to 40 bf16 (80B) => conflict-free ldmatrix.
// ---------------------------------------------------------------------------
__global__ void __launch_bounds__(256)
gemm_tc(const __nv_bfloat16* __restrict__ Ah, const __nv_bfloat16* __restrict__ Al,
        int M,
        const __nv_bfloat16* __restrict__ Bh, const __nv_bfloat16* __restrict__ Bl,
        const float* __restrict__ bias,
        float* __restrict__ C, int ldc)
{
    __shared__ __align__(16) __nv_bfloat16 sAh[128][40];
    __shared__ __align__(16) __nv_bfloat16 sAl[128][40];
    __shared__ __align__(16) __nv_bfloat16 sBh[128][40];
    __shared__ __align__(16) __nv_bfloat16 sBl[128][40];

    const int tid  = threadIdx.x;
    const int wid  = tid >> 5;
    const int lane = tid & 31;
    const int wm   = wid >> 2;      // 0..1
    const int wn   = wid & 3;       // 0..3
    const int bm   = blockIdx.x * 128;
    const int bn   = blockIdx.y * 128;

    const uint32_t sAh_b = (uint32_t)__cvta_generic_to_shared(&sAh[0][0]);
    const uint32_t sAl_b = (uint32_t)__cvta_generic_to_shared(&sAl[0][0]);
    const uint32_t sBh_b = (uint32_t)__cvta_generic_to_shared(&sBh[0][0]);
    const uint32_t sBl_b = (uint32_t)__cvta_generic_to_shared(&sBl[0][0]);

    float acc[4][4][4];
#pragma unroll
    for (int i = 0; i < 4; i++)
#pragma unroll
        for (int j = 0; j < 4; j++)
#pragma unroll
            for (int q = 0; q < 4; q++) acc[i][j][q] = 0.f;

    const int q8 = lane >> 3;       // matrix index within ldmatrix.x4
    const int lg = lane & 7;

    for (int kb = 0; kb < 8; kb++) {
        const int k0 = kb * 32;
        // ---- load tiles: 512 16B-chunks per operand pair ----
#pragma unroll
        for (int it = 0; it < 2; it++) {
            int c = tid + it * 256;
            int row = c >> 2;
            int seg = (c & 3) * 8;
            uint4 vh = make_uint4(0, 0, 0, 0), vl = make_uint4(0, 0, 0, 0);
            if (bm + row < M) {
                vh = *(const uint4*)(Ah + (size_t)(bm + row) * 256 + k0 + seg);
                vl = *(const uint4*)(Al + (size_t)(bm + row) * 256 + k0 + seg);
            }
            *(uint4*)&sAh[row][seg] = vh;
            *(uint4*)&sAl[row][seg] = vl;
            uint4 wh = *(const uint4*)(Bh + (size_t)(bn + row) * 256 + k0 + seg);
            uint4 wl = *(const uint4*)(Bl + (size_t)(bn + row) * 256 + k0 + seg);
            *(uint4*)&sBh[row][seg] = wh;
            *(uint4*)&sBl[row][seg] = wl;
        }
        __syncthreads();

#pragma unroll
        for (int ks = 0; ks < 2; ks++) {
            // ---- B fragments: 4 n-tiles x 2 regs, hi & lo ----
            uint32_t bh[8], bl[8];
#pragma unroll
            for (int np = 0; np < 2; np++) {
                // q0:(n+lg, klo) q1:(n+lg, khi) q2:(n+8+lg, klo) q3:(n+8+lg, khi)
                int nrow = wn * 32 + np * 16 + lg + ((q8 >> 1) ? 8 : 0);
                int bcol = ks * 32 + ((q8 & 1) ? 16 : 0);
                ldsm4(&bh[np * 4], sBh_b + nrow * 80 + bcol);
                ldsm4(&bl[np * 4], sBl_b + nrow * 80 + bcol);
            }
#pragma unroll
            for (int mt = 0; mt < 4; mt++) {
                // q0:(r+lg, klo) q1:(r+8+lg, klo) q2:(r+lg, khi) q3:(r+8+lg, khi)
                int arow = wm * 64 + mt * 16 + lg + ((q8 & 1) ? 8 : 0);
                int acol = ks * 32 + ((q8 >> 1) ? 16 : 0);
                uint32_t ah[4], al[4];
                ldsm4(ah, sAh_b + arow * 80 + acol);
                ldsm4(al, sAl_b + arow * 80 + acol);
#pragma unroll
                for (int nt = 0; nt < 4; nt++) mma_bf16(acc[mt][nt], ah, &bh[nt * 2]);
#pragma unroll
                for (int nt = 0; nt < 4; nt++) mma_bf16(acc[mt][nt], ah, &bl[nt * 2]);
#pragma unroll
                for (int nt = 0; nt < 4; nt++) mma_bf16(acc[mt][nt], al, &bh[nt * 2]);
            }
        }
        __syncthreads();
    }

    // ---- epilogue ----
#pragma unroll
    for (int mt = 0; mt < 4; mt++) {
#pragma unroll
        for (int nt = 0; nt < 4; nt++) {
            int gr0  = bm + wm * 64 + mt * 16 + (lane >> 2);
            int gcol = bn + wn * 32 + nt * 8 + (lane & 3) * 2;
            float b0 = 0.f, b1 = 0.f;
            if (bias) { b0 = bias[gcol]; b1 = bias[gcol + 1]; }
            if (gr0 < M) {
                float2 v = make_float2(acc[mt][nt][0] + b0, acc[mt][nt][1] + b1);
                *(float2*)(C + (size_t)gr0 * ldc + gcol) = v;
            }
            if (gr0 + 8 < M) {
                float2 v = make_float2(acc[mt][nt][2] + b0, acc[mt][nt][3] + b1);
                *(float2*)(C + (size_t)(gr0 + 8) * ldc + gcol) = v;
            }
        }
    }
}

// ---------------------------------------------------------------------------
// Prep kernels
// ---------------------------------------------------------------------------
__global__ void convw_kernel(const float* __restrict__ W,
                             __nv_bfloat16* __restrict__ hi,
                             __nv_bfloat16* __restrict__ lo,
                             int N, int total)   // W[r][k][n], K = 256
{
    int idx = blockIdx.x * blockDim.x + threadIdx.x;
    if (idx >= total) return;
    int n = idx % N;
    int k = (idx / N) & 255;
    int r = idx / (N * 256);
    float f = W[idx];
    __nv_bfloat16 h = __float2bfloat16(f);
    __nv_bfloat16 l = __float2bfloat16(f - __bfloat162float(h));
    size_t o = ((size_t)r * N + n) * 256 + k;
    hi[o] = h;
    lo[o] = l;
}

__global__ void split_kernel(const float* __restrict__ X,
                             __nv_bfloat16* __restrict__ hi,
                             __nv_bfloat16* __restrict__ lo,
                             size_t total, int do_relu)
{
    size_t i = (size_t)blockIdx.x * blockDim.x + threadIdx.x;
    if (i >= total) return;
    float f = X[i];
    if (do_relu) f = fmaxf(f, 0.f);
    __nv_bfloat16 h = __float2bfloat16(f);
    hi[i] = h;
    lo[i] = __float2bfloat16(f - __bfloat162float(h));
}

// ---------------------------------------------------------------------------
// Edge kernels (int32 indices)
// ---------------------------------------------------------------------------
__global__ void zero_int_kernel(int* p, int n)
{
    int i = blockIdx.x * blockDim.x + threadIdx.x;
    if (i < n) p[i] = 0;
}

__global__ void count_kernel(const int* __restrict__ ei,
                             const int* __restrict__ et,
                             int* __restrict__ cnt, int E)
{
    int e = blockIdx.x * blockDim.x + threadIdx.x;
    if (e < E) atomicAdd(&cnt[ei[E + e] * RELS + et[e]], 1);
}

__global__ void __launch_bounds__(256)
scatter_kernel(const float* __restrict__ Y,
               const int* __restrict__ ei,
               const int* __restrict__ et,
               const int* __restrict__ cnt,
               float* __restrict__ out,
               int E, int ldY, int F)
{
    int warp = (blockIdx.x * blockDim.x + threadIdx.x) >> 5;
    int lane = threadIdx.x & 31;
    if (warp >= E) return;

    int src = ei[warp];
    int dst = ei[E + warp];
    int rel = et[warp];
    float norm = 1.0f / (float)max(cnt[dst * RELS + rel], 1);

    const float4* yr = (const float4*)(Y + (size_t)src * ldY + rel * F);
    float* orow = out + (size_t)dst * F;

    int nq = F >> 2;
    for (int i = lane; i < nq; i += 32) {
        float4 v = __ldg(&yr[i]);
        float* p = orow + i * 4;
        atomicAdd(p + 0, v.x * norm);
        atomicAdd(p + 1, v.y * norm);
        atomicAdd(p + 2, v.z * norm);
        atomicAdd(p + 3, v.w * norm);
    }
}

// ---------------------------------------------------------------------------
extern "C" void kernel_launch(void* const* d_in, const int* in_sizes, int n_in,
                              void* d_out, int out_size)
{
    const float* x     = (const float*)d_in[0];
    const int*   ei    = (const int*)d_in[1];
    const int*   et    = (const int*)d_in[2];
    const float* W1    = (const float*)d_in[3];
    const float* root1 = (const float*)d_in[4];
    const float* b1    = (const float*)d_in[5];
    const float* W2    = (const float*)d_in[6];
    const float* root2 = (const float*)d_in[7];
    const float* b2    = (const float*)d_in[8];
    float*       out   = (float*)d_out;

    const int N = in_sizes[0] / 256;
    const int E = in_sizes[2];

    float *Y1, *H, *Y2;
    int* cnt;
    cudaGetSymbolAddress((void**)&Y1, g_Y1);
    cudaGetSymbolAddress((void**)&H,  g_H);
    cudaGetSymbolAddress((void**)&Y2, g_Y2);
    cudaGetSymbolAddress((void**)&cnt, g_cnt);
    __nv_bfloat16 *xh, *xl, *hh, *hl;
    __nv_bfloat16 *w1h, *w1l, *r1h, *r1l, *w2h, *w2l, *r2h, *r2l;
    cudaGetSymbolAddress((void**)&xh, g_xh);
    cudaGetSymbolAddress((void**)&xl, g_xl);
    cudaGetSymbolAddress((void**)&hh, g_hh);
    cudaGetSymbolAddress((void**)&hl, g_hl);
    cudaGetSymbolAddress((void**)&w1h, g_w1h);
    cudaGetSymbolAddress((void**)&w1l, g_w1l);
    cudaGetSymbolAddress((void**)&r1h, g_r1h);
    cudaGetSymbolAddress((void**)&r1l, g_r1l);
    cudaGetSymbolAddress((void**)&w2h, g_w2h);
    cudaGetSymbolAddress((void**)&w2l, g_w2l);
    cudaGetSymbolAddress((void**)&r2h, g_r2h);
    cudaGetSymbolAddress((void**)&r2l, g_r2l);

    // prep
    zero_int_kernel<<<(N * RELS + 255) / 256, 256>>>(cnt, N * RELS);
    count_kernel<<<(E + 255) / 256, 256>>>(ei, et, cnt, E);
    convw_kernel<<<(8 * 256 * 256 + 255) / 256, 256>>>(W1, w1h, w1l, 256, 8 * 256 * 256);
    convw_kernel<<<(256 * 256 + 255) / 256, 256>>>(root1, r1h, r1l, 256, 256 * 256);
    convw_kernel<<<(8 * 256 * 128 + 255) / 256, 256>>>(W2, w2h, w2l, 128, 8 * 256 * 128);
    convw_kernel<<<(256 * 128 + 255) / 256, 256>>>(root2, r2h, r2l, 128, 256 * 128);
    split_kernel<<<(int)(((size_t)N * 256 + 255) / 256), 256>>>(x, xh, xl, (size_t)N * 256, 0);

    const int mtiles = (N + 127) / 128;

    // ---- layer 1 ----
    gemm_tc<<<dim3(mtiles, 16), 256>>>(xh, xl, N, w1h, w1l, nullptr, Y1, 2048);
    gemm_tc<<<dim3(mtiles, 2),  256>>>(xh, xl, N, r1h, r1l, b1, H, 256);
    scatter_kernel<<<(E + 7) / 8, 256>>>(Y1, ei, et, cnt, H, E, 2048, 256);
    split_kernel<<<(int)(((size_t)N * 256 + 255) / 256), 256>>>(H, hh, hl, (size_t)N * 256, 1);

    // ---- layer 2 ----
    gemm_tc<<<dim3(mtiles, 8), 256>>>(hh, hl, N, w2h, w2l, nullptr, Y2, 1024);
    gemm_tc<<<dim3(mtiles, 1), 256>>>(hh, hl, N, r2h, r2l, b2, out, 128);
    scatter_kernel<<<(E + 7) / 8, 256>>>(Y2, ei, et, cnt, out, E, 1024, 128);
}

// round 6
// speedup vs baseline: 2.5598x; 1.2986x over previous
#include <cuda_runtime.h>
#include <cuda_bf16.h>
#include <cstdint>

// ============================================================================
// RGCN 2-layer, transform-first, tensor-core GEMMs (bf16 2-way split via
// mma.sync m16n8k16), CSR-gather aggregation (no global atomics).
// ============================================================================

#define MAXN 50000
#define MAXE 840000
#define RELS 8

__device__ float g_Y1[(size_t)MAXN * 2048];
__device__ float g_H [(size_t)MAXN * 256];
__device__ float g_Y2[(size_t)MAXN * 1024];
__device__ int   g_cnt[MAXN * RELS];
__device__ int   g_deg[MAXN];
__device__ int   g_offs[MAXN + 1];
__device__ int   g_cur[MAXN];
__device__ unsigned g_csr[MAXE];

__device__ __nv_bfloat16 g_xh[(size_t)MAXN * 256];
__device__ __nv_bfloat16 g_xl[(size_t)MAXN * 256];
__device__ __nv_bfloat16 g_hh[(size_t)MAXN * 256];
__device__ __nv_bfloat16 g_hl[(size_t)MAXN * 256];

__device__ __nv_bfloat16 g_w1h[8 * 256 * 256], g_w1l[8 * 256 * 256];
__device__ __nv_bfloat16 g_r1h[256 * 256],     g_r1l[256 * 256];
__device__ __nv_bfloat16 g_w2h[8 * 128 * 256], g_w2l[8 * 128 * 256];
__device__ __nv_bfloat16 g_r2h[128 * 256],     g_r2l[128 * 256];

// ---------------------------------------------------------------------------
__device__ __forceinline__ void ldsm4(uint32_t* r, uint32_t addr)
{
    asm volatile("ldmatrix.sync.aligned.m8n8.x4.shared.b16 {%0,%1,%2,%3}, [%4];"
                 : "=r"(r[0]), "=r"(r[1]), "=r"(r[2]), "=r"(r[3]) : "r"(addr));
}

__device__ __forceinline__ void mma_bf16(float* c, const uint32_t* a, const uint32_t* b)
{
    asm volatile(
        "mma.sync.aligned.m16n8k16.row.col.f32.bf16.bf16.f32 "
        "{%0,%1,%2,%3}, {%4,%5,%6,%7}, {%8,%9}, {%0,%1,%2,%3};"
        : "+f"(c[0]), "+f"(c[1]), "+f"(c[2]), "+f"(c[3])
        : "r"(a[0]), "r"(a[1]), "r"(a[2]), "r"(a[3]), "r"(b[0]), "r"(b[1]));
}

// ---------------------------------------------------------------------------
// GEMM: C[M, T] = A[M,256] @ Bt[T,256]^T (+bias). A,Bt bf16 hi/lo.
// CTA 128x128, 8 warps (2x4 of 64x32), kc=32, 80B smem pitch.
// ---------------------------------------------------------------------------
__global__ void __launch_bounds__(256)
gemm_tc(const __nv_bfloat16* __restrict__ Ah, const __nv_bfloat16* __restrict__ Al,
        int M,
        const __nv_bfloat16* __restrict__ Bh, const __nv_bfloat16* __restrict__ Bl,
        const float* __restrict__ bias,
        float* __restrict__ C, int ldc)
{
    __shared__ __align__(16) __nv_bfloat16 sAh[128][40];
    __shared__ __align__(16) __nv_bfloat16 sAl[128][40];
    __shared__ __align__(16) __nv_bfloat16 sBh[128][40];
    __shared__ __align__(16) __nv_bfloat16 sBl[128][40];

    const int tid  = threadIdx.x;
    const int wid  = tid >> 5;
    const int lane = tid & 31;
    const int wm   = wid >> 2;
    const int wn   = wid & 3;
    const int bm   = blockIdx.x * 128;
    const int bn   = blockIdx.y * 128;

    const uint32_t sAh_b = (uint32_t)__cvta_generic_to_shared(&sAh[0][0]);
    const uint32_t sAl_b = (uint32_t)__cvta_generic_to_shared(&sAl[0][0]);
    const uint32_t sBh_b = (uint32_t)__cvta_generic_to_shared(&sBh[0][0]);
    const uint32_t sBl_b = (uint32_t)__cvta_generic_to_shared(&sBl[0][0]);

    float acc[4][4][4];
#pragma unroll
    for (int i = 0; i < 4; i++)
#pragma unroll
        for (int j = 0; j < 4; j++)
#pragma unroll
            for (int q = 0; q < 4; q++) acc[i][j][q] = 0.f;

    const int q8 = lane >> 3;
    const int lg = lane & 7;

    for (int kb = 0; kb < 8; kb++) {
        const int k0 = kb * 32;
#pragma unroll
        for (int it = 0; it < 2; it++) {
            int c = tid + it * 256;
            int row = c >> 2;
            int seg = (c & 3) * 8;
            uint4 vh = make_uint4(0, 0, 0, 0), vl = make_uint4(0, 0, 0, 0);
            if (bm + row < M) {
                vh = *(const uint4*)(Ah + (size_t)(bm + row) * 256 + k0 + seg);
                vl = *(const uint4*)(Al + (size_t)(bm + row) * 256 + k0 + seg);
            }
            *(uint4*)&sAh[row][seg] = vh;
            *(uint4*)&sAl[row][seg] = vl;
            uint4 wh = *(const uint4*)(Bh + (size_t)(bn + row) * 256 + k0 + seg);
            uint4 wl = *(const uint4*)(Bl + (size_t)(bn + row) * 256 + k0 + seg);
            *(uint4*)&sBh[row][seg] = wh;
            *(uint4*)&sBl[row][seg] = wl;
        }
        __syncthreads();

#pragma unroll
        for (int ks = 0; ks < 2; ks++) {
            uint32_t bh[8], bl[8];
#pragma unroll
            for (int np = 0; np < 2; np++) {
                int nrow = wn * 32 + np * 16 + lg + ((q8 >> 1) ? 8 : 0);
                int bcol = ks * 32 + ((q8 & 1) ? 16 : 0);
                ldsm4(&bh[np * 4], sBh_b + nrow * 80 + bcol);
                ldsm4(&bl[np * 4], sBl_b + nrow * 80 + bcol);
            }
#pragma unroll
            for (int mt = 0; mt < 4; mt++) {
                int arow = wm * 64 + mt * 16 + lg + ((q8 & 1) ? 8 : 0);
                int acol = ks * 32 + ((q8 >> 1) ? 16 : 0);
                uint32_t ah[4], al[4];
                ldsm4(ah, sAh_b + arow * 80 + acol);
                ldsm4(al, sAl_b + arow * 80 + acol);
#pragma unroll
                for (int nt = 0; nt < 4; nt++) mma_bf16(acc[mt][nt], ah, &bh[nt * 2]);
#pragma unroll
                for (int nt = 0; nt < 4; nt++) mma_bf16(acc[mt][nt], ah, &bl[nt * 2]);
#pragma unroll
                for (int nt = 0; nt < 4; nt++) mma_bf16(acc[mt][nt], al, &bh[nt * 2]);
            }
        }
        __syncthreads();
    }

#pragma unroll
    for (int mt = 0; mt < 4; mt++) {
#pragma unroll
        for (int nt = 0; nt < 4; nt++) {
            int gr0  = bm + wm * 64 + mt * 16 + (lane >> 2);
            int gcol = bn + wn * 32 + nt * 8 + (lane & 3) * 2;
            float b0 = 0.f, b1 = 0.f;
            if (bias) { b0 = bias[gcol]; b1 = bias[gcol + 1]; }
            if (gr0 < M) {
                float2 v = make_float2(acc[mt][nt][0] + b0, acc[mt][nt][1] + b1);
                *(float2*)(C + (size_t)gr0 * ldc + gcol) = v;
            }
            if (gr0 + 8 < M) {
                float2 v = make_float2(acc[mt][nt][2] + b0, acc[mt][nt][3] + b1);
                *(float2*)(C + (size_t)(gr0 + 8) * ldc + gcol) = v;
            }
        }
    }
}

// ---------------------------------------------------------------------------
// Prep kernels
// ---------------------------------------------------------------------------
__global__ void convw_kernel(const float* __restrict__ W,
                             __nv_bfloat16* __restrict__ hi,
                             __nv_bfloat16* __restrict__ lo,
                             int N, int total)
{
    int idx = blockIdx.x * blockDim.x + threadIdx.x;
    if (idx >= total) return;
    int n = idx % N;
    int k = (idx / N) & 255;
    int r = idx / (N * 256);
    float f = W[idx];
    __nv_bfloat16 h = __float2bfloat16(f);
    __nv_bfloat16 l = __float2bfloat16(f - __bfloat162float(h));
    size_t o = ((size_t)r * N + n) * 256 + k;
    hi[o] = h;
    lo[o] = l;
}

__global__ void split_kernel(const float* __restrict__ X,
                             __nv_bfloat16* __restrict__ hi,
                             __nv_bfloat16* __restrict__ lo,
                             size_t total)
{
    size_t i = (size_t)blockIdx.x * blockDim.x + threadIdx.x;
    if (i >= total) return;
    float f = X[i];
    __nv_bfloat16 h = __float2bfloat16(f);
    hi[i] = h;
    lo[i] = __float2bfloat16(f - __bfloat162float(h));
}

// ---------------------------------------------------------------------------
// CSR construction
// ---------------------------------------------------------------------------
__global__ void zero_int_kernel(int* p, int n)
{
    int i = blockIdx.x * blockDim.x + threadIdx.x;
    if (i < n) p[i] = 0;
}

__global__ void count_kernel(const int* __restrict__ ei,
                             const int* __restrict__ et,
                             int* __restrict__ cnt, int E)
{
    int e = blockIdx.x * blockDim.x + threadIdx.x;
    if (e < E) atomicAdd(&cnt[ei[E + e] * RELS + et[e]], 1);
}

__global__ void deg_kernel(const int* __restrict__ cnt, int* __restrict__ deg, int n)
{
    int i = blockIdx.x * blockDim.x + threadIdx.x;
    if (i < n) {
        int s = 0;
#pragma unroll
        for (int r = 0; r < RELS; r++) s += cnt[i * RELS + r];
        deg[i] = s;
    }
}

// single-CTA exclusive scan (n up to ~64k elements is fine)
__global__ void scan_kernel(const int* __restrict__ deg, int* __restrict__ offs, int n)
{
    __shared__ int buf[1024];
    __shared__ int carry;
    const int tid = threadIdx.x;
    if (tid == 0) carry = 0;
    __syncthreads();
    for (int base = 0; base < n; base += 1024) {
        int i = base + tid;
        int v = (i < n) ? deg[i] : 0;
        buf[tid] = v;
        __syncthreads();
        for (int d = 1; d < 1024; d <<= 1) {
            int t = (tid >= d) ? buf[tid - d] : 0;
            __syncthreads();
            buf[tid] += t;
            __syncthreads();
        }
        if (i < n) offs[i] = carry + buf[tid] - v;
        __syncthreads();
        if (tid == 0) carry += buf[1023];
        __syncthreads();
    }
    if (tid == 0) offs[n] = carry;
}

__global__ void fill_kernel(const int* __restrict__ ei,
                            const int* __restrict__ et,
                            const int* __restrict__ offs,
                            int* __restrict__ cur,
                            unsigned* __restrict__ csr, int E)
{
    int e = blockIdx.x * blockDim.x + threadIdx.x;
    if (e < E) {
        int d = ei[E + e];
        int pos = offs[d] + atomicAdd(&cur[d], 1);
        csr[pos] = (unsigned)ei[e] | ((unsigned)et[e] << 16);
    }
}

// ---------------------------------------------------------------------------
// Gather-aggregation (pull). Layer 1: +root part, relu, split to bf16 hi/lo.
// ---------------------------------------------------------------------------
__global__ void __launch_bounds__(256)
gather1_kernel(const float* __restrict__ Y,
               const unsigned* __restrict__ csr,
               const int* __restrict__ offs,
               const int* __restrict__ cnt,
               const float* __restrict__ Hroot,
               __nv_bfloat16* __restrict__ hh,
               __nv_bfloat16* __restrict__ hl)
{
    const int dst = blockIdx.x;
    const int tid = threadIdx.x;
    __shared__ float nrm[8];
    if (tid < 8) nrm[tid] = 1.0f / (float)max(cnt[dst * RELS + tid], 1);
    const int s = offs[dst], t = offs[dst + 1];
    __syncthreads();

    float acc = Hroot[(size_t)dst * 256 + tid];
    int e = s;
    for (; e + 4 <= t; e += 4) {
        unsigned p0 = csr[e], p1 = csr[e + 1], p2 = csr[e + 2], p3 = csr[e + 3];
        float y0 = __ldg(Y + (size_t)(p0 & 0xFFFFu) * 2048 + (p0 >> 16) * 256 + tid);
        float y1 = __ldg(Y + (size_t)(p1 & 0xFFFFu) * 2048 + (p1 >> 16) * 256 + tid);
        float y2 = __ldg(Y + (size_t)(p2 & 0xFFFFu) * 2048 + (p2 >> 16) * 256 + tid);
        float y3 = __ldg(Y + (size_t)(p3 & 0xFFFFu) * 2048 + (p3 >> 16) * 256 + tid);
        acc += y0 * nrm[p0 >> 16] + y1 * nrm[p1 >> 16]
             + y2 * nrm[p2 >> 16] + y3 * nrm[p3 >> 16];
    }
    for (; e < t; e++) {
        unsigned p = csr[e];
        acc += __ldg(Y + (size_t)(p & 0xFFFFu) * 2048 + (p >> 16) * 256 + tid) * nrm[p >> 16];
    }

    acc = fmaxf(acc, 0.f);
    __nv_bfloat16 h = __float2bfloat16(acc);
    hh[(size_t)dst * 256 + tid] = h;
    hl[(size_t)dst * 256 + tid] = __float2bfloat16(acc - __bfloat162float(h));
}

// Layer 2: accumulate into out (root part already written there).
__global__ void __launch_bounds__(128)
gather2_kernel(const float* __restrict__ Y,
               const unsigned* __restrict__ csr,
               const int* __restrict__ offs,
               const int* __restrict__ cnt,
               float* __restrict__ out)
{
    const int dst = blockIdx.x;
    const int tid = threadIdx.x;
    __shared__ float nrm[8];
    if (tid < 8) nrm[tid] = 1.0f / (float)max(cnt[dst * RELS + tid], 1);
    const int s = offs[dst], t = offs[dst + 1];
    __syncthreads();

    float acc = out[(size_t)dst * 128 + tid];
    int e = s;
    for (; e + 4 <= t; e += 4) {
        unsigned p0 = csr[e], p1 = csr[e + 1], p2 = csr[e + 2], p3 = csr[e + 3];
        float y0 = __ldg(Y + (size_t)(p0 & 0xFFFFu) * 1024 + (p0 >> 16) * 128 + tid);
        float y1 = __ldg(Y + (size_t)(p1 & 0xFFFFu) * 1024 + (p1 >> 16) * 128 + tid);
        float y2 = __ldg(Y + (size_t)(p2 & 0xFFFFu) * 1024 + (p2 >> 16) * 128 + tid);
        float y3 = __ldg(Y + (size_t)(p3 & 0xFFFFu) * 1024 + (p3 >> 16) * 128 + tid);
        acc += y0 * nrm[p0 >> 16] + y1 * nrm[p1 >> 16]
             + y2 * nrm[p2 >> 16] + y3 * nrm[p3 >> 16];
    }
    for (; e < t; e++) {
        unsigned p = csr[e];
        acc += __ldg(Y + (size_t)(p & 0xFFFFu) * 1024 + (p >> 16) * 128 + tid) * nrm[p >> 16];
    }
    out[(size_t)dst * 128 + tid] = acc;
}

// ---------------------------------------------------------------------------
extern "C" void kernel_launch(void* const* d_in, const int* in_sizes, int n_in,
                              void* d_out, int out_size)
{
    const float* x     = (const float*)d_in[0];
    const int*   ei    = (const int*)d_in[1];
    const int*   et    = (const int*)d_in[2];
    const float* W1    = (const float*)d_in[3];
    const float* root1 = (const float*)d_in[4];
    const float* b1    = (const float*)d_in[5];
    const float* W2    = (const float*)d_in[6];
    const float* root2 = (const float*)d_in[7];
    const float* b2    = (const float*)d_in[8];
    float*       out   = (float*)d_out;

    const int N = in_sizes[0] / 256;
    const int E = in_sizes[2];

    float *Y1, *H, *Y2;
    int *cnt, *deg, *offs, *cur;
    unsigned* csr;
    cudaGetSymbolAddress((void**)&Y1, g_Y1);
    cudaGetSymbolAddress((void**)&H,  g_H);
    cudaGetSymbolAddress((void**)&Y2, g_Y2);
    cudaGetSymbolAddress((void**)&cnt, g_cnt);
    cudaGetSymbolAddress((void**)&deg, g_deg);
    cudaGetSymbolAddress((void**)&offs, g_offs);
    cudaGetSymbolAddress((void**)&cur, g_cur);
    cudaGetSymbolAddress((void**)&csr, g_csr);
    __nv_bfloat16 *xh, *xl, *hh, *hl;
    __nv_bfloat16 *w1h, *w1l, *r1h, *r1l, *w2h, *w2l, *r2h, *r2l;
    cudaGetSymbolAddress((void**)&xh, g_xh);
    cudaGetSymbolAddress((void**)&xl, g_xl);
    cudaGetSymbolAddress((void**)&hh, g_hh);
    cudaGetSymbolAddress((void**)&hl, g_hl);
    cudaGetSymbolAddress((void**)&w1h, g_w1h);
    cudaGetSymbolAddress((void**)&w1l, g_w1l);
    cudaGetSymbolAddress((void**)&r1h, g_r1h);
    cudaGetSymbolAddress((void**)&r1l, g_r1l);
    cudaGetSymbolAddress((void**)&w2h, g_w2h);
    cudaGetSymbolAddress((void**)&w2l, g_w2l);
    cudaGetSymbolAddress((void**)&r2h, g_r2h);
    cudaGetSymbolAddress((void**)&r2l, g_r2l);

    // ---- CSR build ----
    zero_int_kernel<<<(N * RELS + 255) / 256, 256>>>(cnt, N * RELS);
    zero_int_kernel<<<(N + 255) / 256, 256>>>(cur, N);
    count_kernel<<<(E + 255) / 256, 256>>>(ei, et, cnt, E);
    deg_kernel<<<(N + 255) / 256, 256>>>(cnt, deg, N);
    scan_kernel<<<1, 1024>>>(deg, offs, N);
    fill_kernel<<<(E + 255) / 256, 256>>>(ei, et, offs, cur, csr, E);

    // ---- weight + input prep ----
    convw_kernel<<<(8 * 256 * 256 + 255) / 256, 256>>>(W1, w1h, w1l, 256, 8 * 256 * 256);
    convw_kernel<<<(256 * 256 + 255) / 256, 256>>>(root1, r1h, r1l, 256, 256 * 256);
    convw_kernel<<<(8 * 256 * 128 + 255) / 256, 256>>>(W2, w2h, w2l, 128, 8 * 256 * 128);
    convw_kernel<<<(256 * 128 + 255) / 256, 256>>>(root2, r2h, r2l, 128, 256 * 128);
    split_kernel<<<(int)(((size_t)N * 256 + 255) / 256), 256>>>(x, xh, xl, (size_t)N * 256);

    const int mtiles = (N + 127) / 128;

    // ---- layer 1 ----
    gemm_tc<<<dim3(mtiles, 16), 256>>>(xh, xl, N, w1h, w1l, nullptr, Y1, 2048);
    gemm_tc<<<dim3(mtiles, 2),  256>>>(xh, xl, N, r1h, r1l, b1, H, 256);
    gather1_kernel<<<N, 256>>>(Y1, csr, offs, cnt, H, hh, hl);

    // ---- layer 2 ----
    gemm_tc<<<dim3(mtiles, 8), 256>>>(hh, hl, N, w2h, w2l, nullptr, Y2, 1024);
    gemm_tc<<<dim3(mtiles, 1), 256>>>(hh, hl, N, r2h, r2l, b2, out, 128);
    gather2_kernel<<<N, 128>>>(Y2, csr, offs, cnt, out);
}

// round 7
// speedup vs baseline: 3.1523x; 1.2315x over previous
#include <cuda_runtime.h>
#include <cuda_bf16.h>
#include <cuda_fp16.h>
#include <cstdint>

// ============================================================================
// RGCN 2-layer, transform-first. GEMMs: mma.sync bf16 2-way split, cp.async
// double-buffered. Messages (Y) stored fp16. CSR pull aggregation (no atomics).
// ============================================================================

#define MAXN 50000
#define MAXE 840000
#define RELS 8

__device__ __half g_Y1[(size_t)MAXN * 2048];
__device__ float  g_H [(size_t)MAXN * 256];
__device__ __half g_Y2[(size_t)MAXN * 1024];
__device__ int    g_cnt[MAXN * RELS];
__device__ int    g_deg[MAXN];
__device__ int    g_offs[MAXN + 1];
__device__ int    g_cur[MAXN];
__device__ unsigned g_csr[MAXE];

__device__ __nv_bfloat16 g_xh[(size_t)MAXN * 256];
__device__ __nv_bfloat16 g_xl[(size_t)MAXN * 256];
__device__ __nv_bfloat16 g_hh[(size_t)MAXN * 256];
__device__ __nv_bfloat16 g_hl[(size_t)MAXN * 256];

__device__ __nv_bfloat16 g_w1h[8 * 256 * 256], g_w1l[8 * 256 * 256];
__device__ __nv_bfloat16 g_r1h[256 * 256],     g_r1l[256 * 256];
__device__ __nv_bfloat16 g_w2h[8 * 128 * 256], g_w2l[8 * 128 * 256];
__device__ __nv_bfloat16 g_r2h[128 * 256],     g_r2l[128 * 256];

// ---------------------------------------------------------------------------
__device__ __forceinline__ void ldsm4(uint32_t* r, uint32_t addr)
{
    asm volatile("ldmatrix.sync.aligned.m8n8.x4.shared.b16 {%0,%1,%2,%3}, [%4];"
                 : "=r"(r[0]), "=r"(r[1]), "=r"(r[2]), "=r"(r[3]) : "r"(addr));
}

__device__ __forceinline__ void mma_bf16(float* c, const uint32_t* a, const uint32_t* b)
{
    asm volatile(
        "mma.sync.aligned.m16n8k16.row.col.f32.bf16.bf16.f32 "
        "{%0,%1,%2,%3}, {%4,%5,%6,%7}, {%8,%9}, {%0,%1,%2,%3};"
        : "+f"(c[0]), "+f"(c[1]), "+f"(c[2]), "+f"(c[3])
        : "r"(a[0]), "r"(a[1]), "r"(a[2]), "r"(a[3]), "r"(b[0]), "r"(b[1]));
}

#define CP_COMMIT() asm volatile("cp.async.commit_group;" ::: "memory")
#define CP_WAIT1()  asm volatile("cp.async.wait_group 1;" ::: "memory")
#define CP_WAIT0()  asm volatile("cp.async.wait_group 0;" ::: "memory")

__device__ __forceinline__ void cp16(uint32_t dst, const void* src, int sz)
{
    asm volatile("cp.async.ca.shared.global [%0], [%1], 16, %2;"
                 :: "r"(dst), "l"(src), "r"(sz));
}

// ---------------------------------------------------------------------------
// Pipelined GEMM: C[M,T] = A[M,256] @ Bt[T,256]^T (+bias), A/Bt bf16 hi/lo.
// CTA 128x128, 8 warps (2x4 of 64x32), kc=32, 2-stage cp.async.
// smem per stage: 4 operands x 128 rows x 80B pitch = 40960 B. Total 80 KB.
// ---------------------------------------------------------------------------
#define OP_BYTES 10240
#define STG_BYTES 40960
#define SMEMP (2 * STG_BYTES)

template <typename OutT>
__global__ void __launch_bounds__(256)
gemm_pipe(const __nv_bfloat16* __restrict__ Ah, const __nv_bfloat16* __restrict__ Al,
          int M,
          const __nv_bfloat16* __restrict__ Bh, const __nv_bfloat16* __restrict__ Bl,
          const float* __restrict__ bias,
          OutT* __restrict__ C, int ldc)
{
    extern __shared__ char smem[];
    uint32_t sb0;
    asm("{ .reg .u64 t; cvta.to.shared.u64 t, %1; cvt.u32.u64 %0, t; }"
        : "=r"(sb0) : "l"(smem));

    const int tid  = threadIdx.x;
    const int wid  = tid >> 5;
    const int lane = tid & 31;
    const int wm   = wid >> 2;
    const int wn   = wid & 3;
    const int bm   = blockIdx.x * 128;
    const int bn   = blockIdx.y * 128;

    float acc[4][4][4];
#pragma unroll
    for (int i = 0; i < 4; i++)
#pragma unroll
        for (int j = 0; j < 4; j++)
#pragma unroll
            for (int q = 0; q < 4; q++) acc[i][j][q] = 0.f;

    const int q8 = lane >> 3;
    const int lg = lane & 7;

    // stage loader: 2048 16B chunks, 8 per thread, operand = i>>1
    auto load_stage = [&](int stage, int k0) {
        uint32_t sb = sb0 + stage * STG_BYTES;
#pragma unroll
        for (int i = 0; i < 8; i++) {
            int c   = tid + i * 256;
            int op  = i >> 1;
            int idx = c & 511;
            int row = idx >> 2;
            int seg = (idx & 3) * 8;
            const __nv_bfloat16* g;
            int grow;
            int sz = 16;
            if (op == 0)      { g = Ah; grow = bm + row; if (grow >= M) { grow = 0; sz = 0; } }
            else if (op == 1) { g = Al; grow = bm + row; if (grow >= M) { grow = 0; sz = 0; } }
            else if (op == 2) { g = Bh; grow = bn + row; }
            else              { g = Bl; grow = bn + row; }
            cp16(sb + op * OP_BYTES + row * 80 + seg * 2,
                 g + (size_t)grow * 256 + k0 + seg, sz);
        }
        CP_COMMIT();
    };

    load_stage(0, 0);

    for (int kb = 0; kb < 8; kb++) {
        if (kb < 7) load_stage((kb + 1) & 1, (kb + 1) * 32);
        if (kb < 7) CP_WAIT1(); else CP_WAIT0();
        __syncthreads();

        const uint32_t sb = sb0 + (kb & 1) * STG_BYTES;
        const uint32_t sAh_b = sb;
        const uint32_t sAl_b = sb + OP_BYTES;
        const uint32_t sBh_b = sb + 2 * OP_BYTES;
        const uint32_t sBl_b = sb + 3 * OP_BYTES;

#pragma unroll
        for (int ks = 0; ks < 2; ks++) {
            uint32_t bh[8], bl[8];
#pragma unroll
            for (int np = 0; np < 2; np++) {
                int nrow = wn * 32 + np * 16 + lg + ((q8 >> 1) ? 8 : 0);
                int bcol = ks * 32 + ((q8 & 1) ? 16 : 0);
                ldsm4(&bh[np * 4], sBh_b + nrow * 80 + bcol);
                ldsm4(&bl[np * 4], sBl_b + nrow * 80 + bcol);
            }
#pragma unroll
            for (int mt = 0; mt < 4; mt++) {
                int arow = wm * 64 + mt * 16 + lg + ((q8 & 1) ? 8 : 0);
                int acol = ks * 32 + ((q8 >> 1) ? 16 : 0);
                uint32_t ah[4], al[4];
                ldsm4(ah, sAh_b + arow * 80 + acol);
                ldsm4(al, sAl_b + arow * 80 + acol);
#pragma unroll
                for (int nt = 0; nt < 4; nt++) mma_bf16(acc[mt][nt], ah, &bh[nt * 2]);
#pragma unroll
                for (int nt = 0; nt < 4; nt++) mma_bf16(acc[mt][nt], ah, &bl[nt * 2]);
#pragma unroll
                for (int nt = 0; nt < 4; nt++) mma_bf16(acc[mt][nt], al, &bh[nt * 2]);
            }
        }
        __syncthreads();
    }

    // ---- epilogue ----
#pragma unroll
    for (int mt = 0; mt < 4; mt++) {
#pragma unroll
        for (int nt = 0; nt < 4; nt++) {
            int gr0  = bm + wm * 64 + mt * 16 + (lane >> 2);
            int gcol = bn + wn * 32 + nt * 8 + (lane & 3) * 2;
            float b0 = 0.f, b1 = 0.f;
            if (bias) { b0 = bias[gcol]; b1 = bias[gcol + 1]; }
#pragma unroll
            for (int h = 0; h < 2; h++) {
                int gr = gr0 + h * 8;
                if (gr < M) {
                    float v0 = acc[mt][nt][h * 2 + 0] + b0;
                    float v1 = acc[mt][nt][h * 2 + 1] + b1;
                    if (sizeof(OutT) == 4) {
                        *(float2*)((float*)C + (size_t)gr * ldc + gcol) = make_float2(v0, v1);
                    } else {
                        *(__half2*)((__half*)C + (size_t)gr * ldc + gcol) = __floats2half2_rn(v0, v1);
                    }
                }
            }
        }
    }
}

// ---------------------------------------------------------------------------
// Prep kernels
// ---------------------------------------------------------------------------
__global__ void convw_kernel(const float* __restrict__ W,
                             __nv_bfloat16* __restrict__ hi,
                             __nv_bfloat16* __restrict__ lo,
                             int N, int total)
{
    int idx = blockIdx.x * blockDim.x + threadIdx.x;
    if (idx >= total) return;
    int n = idx % N;
    int k = (idx / N) & 255;
    int r = idx / (N * 256);
    float f = W[idx];
    __nv_bfloat16 h = __float2bfloat16(f);
    __nv_bfloat16 l = __float2bfloat16(f - __bfloat162float(h));
    size_t o = ((size_t)r * N + n) * 256 + k;
    hi[o] = h;
    lo[o] = l;
}

__global__ void split_kernel(const float* __restrict__ X,
                             __nv_bfloat16* __restrict__ hi,
                             __nv_bfloat16* __restrict__ lo,
                             size_t total)
{
    size_t i = (size_t)blockIdx.x * blockDim.x + threadIdx.x;
    if (i >= total) return;
    float f = X[i];
    __nv_bfloat16 h = __float2bfloat16(f);
    hi[i] = h;
    lo[i] = __float2bfloat16(f - __bfloat162float(h));
}

// ---------------------------------------------------------------------------
// CSR construction
// ---------------------------------------------------------------------------
__global__ void zero_int_kernel(int* p, int n)
{
    int i = blockIdx.x * blockDim.x + threadIdx.x;
    if (i < n) p[i] = 0;
}

__global__ void count_kernel(const int* __restrict__ ei,
                             const int* __restrict__ et,
                             int* __restrict__ cnt, int E)
{
    int e = blockIdx.x * blockDim.x + threadIdx.x;
    if (e < E) atomicAdd(&cnt[ei[E + e] * RELS + et[e]], 1);
}

__global__ void deg_kernel(const int* __restrict__ cnt, int* __restrict__ deg, int n)
{
    int i = blockIdx.x * blockDim.x + threadIdx.x;
    if (i < n) {
        int s = 0;
#pragma unroll
        for (int r = 0; r < RELS; r++) s += cnt[i * RELS + r];
        deg[i] = s;
    }
}

__global__ void scan_kernel(const int* __restrict__ deg, int* __restrict__ offs, int n)
{
    __shared__ int buf[1024];
    __shared__ int carry;
    const int tid = threadIdx.x;
    if (tid == 0) carry = 0;
    __syncthreads();
    for (int base = 0; base < n; base += 1024) {
        int i = base + tid;
        int v = (i < n) ? deg[i] : 0;
        buf[tid] = v;
        __syncthreads();
        for (int d = 1; d < 1024; d <<= 1) {
            int t = (tid >= d) ? buf[tid - d] : 0;
            __syncthreads();
            buf[tid] += t;
            __syncthreads();
        }
        if (i < n) offs[i] = carry + buf[tid] - v;
        __syncthreads();
        if (tid == 0) carry += buf[1023];
        __syncthreads();
    }
    if (tid == 0) offs[n] = carry;
}

__global__ void fill_kernel(const int* __restrict__ ei,
                            const int* __restrict__ et,
                            const int* __restrict__ offs,
                            int* __restrict__ cur,
                            unsigned* __restrict__ csr, int E)
{
    int e = blockIdx.x * blockDim.x + threadIdx.x;
    if (e < E) {
        int d = ei[E + e];
        int pos = offs[d] + atomicAdd(&cur[d], 1);
        csr[pos] = (unsigned)ei[e] | ((unsigned)et[e] << 16);
    }
}

// ---------------------------------------------------------------------------
// Gather aggregation. Layer 1: + root, relu, bf16 hi/lo split. 128 thr, half2.
// ---------------------------------------------------------------------------
__global__ void __launch_bounds__(128)
gather1_kernel(const __half* __restrict__ Y,
               const unsigned* __restrict__ csr,
               const int* __restrict__ offs,
               const int* __restrict__ cnt,
               const float* __restrict__ Hroot,
               __nv_bfloat16* __restrict__ hh,
               __nv_bfloat16* __restrict__ hl)
{
    const int dst = blockIdx.x;
    const int tid = threadIdx.x;
    __shared__ float nrm[8];
    if (tid < 8) nrm[tid] = 1.0f / (float)max(cnt[dst * RELS + tid], 1);
    const int s = offs[dst], t = offs[dst + 1];
    __syncthreads();

    float2 acc = *(const float2*)(Hroot + (size_t)dst * 256 + tid * 2);
    int e = s;
    for (; e + 4 <= t; e += 4) {
        unsigned p0 = csr[e], p1 = csr[e + 1], p2 = csr[e + 2], p3 = csr[e + 3];
        __half2 y0 = __ldg((const __half2*)(Y + (size_t)(p0 & 0xFFFFu) * 2048 + (p0 >> 16) * 256) + tid);
        __half2 y1 = __ldg((const __half2*)(Y + (size_t)(p1 & 0xFFFFu) * 2048 + (p1 >> 16) * 256) + tid);
        __half2 y2 = __ldg((const __half2*)(Y + (size_t)(p2 & 0xFFFFu) * 2048 + (p2 >> 16) * 256) + tid);
        __half2 y3 = __ldg((const __half2*)(Y + (size_t)(p3 & 0xFFFFu) * 2048 + (p3 >> 16) * 256) + tid);
        float2 f0 = __half22float2(y0), f1 = __half22float2(y1);
        float2 f2 = __half22float2(y2), f3 = __half22float2(y3);
        float n0 = nrm[p0 >> 16], n1 = nrm[p1 >> 16], n2 = nrm[p2 >> 16], n3 = nrm[p3 >> 16];
        acc.x += f0.x * n0 + f1.x * n1 + f2.x * n2 + f3.x * n3;
        acc.y += f0.y * n0 + f1.y * n1 + f2.y * n2 + f3.y * n3;
    }
    for (; e < t; e++) {
        unsigned p = csr[e];
        __half2 y = __ldg((const __half2*)(Y + (size_t)(p & 0xFFFFu) * 2048 + (p >> 16) * 256) + tid);
        float2 f = __half22float2(y);
        float n = nrm[p >> 16];
        acc.x += f.x * n;
        acc.y += f.y * n;
    }

    acc.x = fmaxf(acc.x, 0.f);
    acc.y = fmaxf(acc.y, 0.f);
    __nv_bfloat16 h0 = __float2bfloat16(acc.x);
    __nv_bfloat16 h1 = __float2bfloat16(acc.y);
    __nv_bfloat16 l0 = __float2bfloat16(acc.x - __bfloat162float(h0));
    __nv_bfloat16 l1 = __float2bfloat16(acc.y - __bfloat162float(h1));
    uint32_t ph = (uint32_t)__bfloat16_as_ushort(h0) | ((uint32_t)__bfloat16_as_ushort(h1) << 16);
    uint32_t pl = (uint32_t)__bfloat16_as_ushort(l0) | ((uint32_t)__bfloat16_as_ushort(l1) << 16);
    *(uint32_t*)(hh + (size_t)dst * 256 + tid * 2) = ph;
    *(uint32_t*)(hl + (size_t)dst * 256 + tid * 2) = pl;
}

// Layer 2: accumulate into out (root already there). 64 thr, half2.
__global__ void __launch_bounds__(64)
gather2_kernel(const __half* __restrict__ Y,
               const unsigned* __restrict__ csr,
               const int* __restrict__ offs,
               const int* __restrict__ cnt,
               float* __restrict__ out)
{
    const int dst = blockIdx.x;
    const int tid = threadIdx.x;
    __shared__ float nrm[8];
    if (tid < 8) nrm[tid] = 1.0f / (float)max(cnt[dst * RELS + tid], 1);
    const int s = offs[dst], t = offs[dst + 1];
    __syncthreads();

    float2 acc = *(const float2*)(out + (size_t)dst * 128 + tid * 2);
    int e = s;
    for (; e + 4 <= t; e += 4) {
        unsigned p0 = csr[e], p1 = csr[e + 1], p2 = csr[e + 2], p3 = csr[e + 3];
        __half2 y0 = __ldg((const __half2*)(Y + (size_t)(p0 & 0xFFFFu) * 1024 + (p0 >> 16) * 128) + tid);
        __half2 y1 = __ldg((const __half2*)(Y + (size_t)(p1 & 0xFFFFu) * 1024 + (p1 >> 16) * 128) + tid);
        __half2 y2 = __ldg((const __half2*)(Y + (size_t)(p2 & 0xFFFFu) * 1024 + (p2 >> 16) * 128) + tid);
        __half2 y3 = __ldg((const __half2*)(Y + (size_t)(p3 & 0xFFFFu) * 1024 + (p3 >> 16) * 128) + tid);
        float2 f0 = __half22float2(y0), f1 = __half22float2(y1);
        float2 f2 = __half22float2(y2), f3 = __half22float2(y3);
        float n0 = nrm[p0 >> 16], n1 = nrm[p1 >> 16], n2 = nrm[p2 >> 16], n3 = nrm[p3 >> 16];
        acc.x += f0.x * n0 + f1.x * n1 + f2.x * n2 + f3.x * n3;
        acc.y += f0.y * n0 + f1.y * n1 + f2.y * n2 + f3.y * n3;
    }
    for (; e < t; e++) {
        unsigned p = csr[e];
        __half2 y = __ldg((const __half2*)(Y + (size_t)(p & 0xFFFFu) * 1024 + (p >> 16) * 128) + tid);
        float2 f = __half22float2(y);
        float n = nrm[p >> 16];
        acc.x += f.x * n;
        acc.y += f.y * n;
    }
    *(float2*)(out + (size_t)dst * 128 + tid * 2) = acc;
}

// ---------------------------------------------------------------------------
extern "C" void kernel_launch(void* const* d_in, const int* in_sizes, int n_in,
                              void* d_out, int out_size)
{
    const float* x     = (const float*)d_in[0];
    const int*   ei    = (const int*)d_in[1];
    const int*   et    = (const int*)d_in[2];
    const float* W1    = (const float*)d_in[3];
    const float* root1 = (const float*)d_in[4];
    const float* b1    = (const float*)d_in[5];
    const float* W2    = (const float*)d_in[6];
    const float* root2 = (const float*)d_in[7];
    const float* b2    = (const float*)d_in[8];
    float*       out   = (float*)d_out;

    const int N = in_sizes[0] / 256;
    const int E = in_sizes[2];

    __half *Y1, *Y2;
    float* H;
    int *cnt, *deg, *offs, *cur;
    unsigned* csr;
    cudaGetSymbolAddress((void**)&Y1, g_Y1);
    cudaGetSymbolAddress((void**)&H,  g_H);
    cudaGetSymbolAddress((void**)&Y2, g_Y2);
    cudaGetSymbolAddress((void**)&cnt, g_cnt);
    cudaGetSymbolAddress((void**)&deg, g_deg);
    cudaGetSymbolAddress((void**)&offs, g_offs);
    cudaGetSymbolAddress((void**)&cur, g_cur);
    cudaGetSymbolAddress((void**)&csr, g_csr);
    __nv_bfloat16 *xh, *xl, *hh, *hl;
    __nv_bfloat16 *w1h, *w1l, *r1h, *r1l, *w2h, *w2l, *r2h, *r2l;
    cudaGetSymbolAddress((void**)&xh, g_xh);
    cudaGetSymbolAddress((void**)&xl, g_xl);
    cudaGetSymbolAddress((void**)&hh, g_hh);
    cudaGetSymbolAddress((void**)&hl, g_hl);
    cudaGetSymbolAddress((void**)&w1h, g_w1h);
    cudaGetSymbolAddress((void**)&w1l, g_w1l);
    cudaGetSymbolAddress((void**)&r1h, g_r1h);
    cudaGetSymbolAddress((void**)&r1l, g_r1l);
    cudaGetSymbolAddress((void**)&w2h, g_w2h);
    cudaGetSymbolAddress((void**)&w2l, g_w2l);
    cudaGetSymbolAddress((void**)&r2h, g_r2h);
    cudaGetSymbolAddress((void**)&r2l, g_r2l);

    static int attr_set = 0;
    if (!attr_set) {
        cudaFuncSetAttribute(gemm_pipe<__half>, cudaFuncAttributeMaxDynamicSharedMemorySize, SMEMP);
        cudaFuncSetAttribute(gemm_pipe<float>,  cudaFuncAttributeMaxDynamicSharedMemorySize, SMEMP);
        attr_set = 1;
    }

    // ---- CSR build ----
    zero_int_kernel<<<(N * RELS + 255) / 256, 256>>>(cnt, N * RELS);
    zero_int_kernel<<<(N + 255) / 256, 256>>>(cur, N);
    count_kernel<<<(E + 255) / 256, 256>>>(ei, et, cnt, E);
    deg_kernel<<<(N + 255) / 256, 256>>>(cnt, deg, N);
    scan_kernel<<<1, 1024>>>(deg, offs, N);
    fill_kernel<<<(E + 255) / 256, 256>>>(ei, et, offs, cur, csr, E);

    // ---- weight + input prep ----
    convw_kernel<<<(8 * 256 * 256 + 255) / 256, 256>>>(W1, w1h, w1l, 256, 8 * 256 * 256);
    convw_kernel<<<(256 * 256 + 255) / 256, 256>>>(root1, r1h, r1l, 256, 256 * 256);
    convw_kernel<<<(8 * 256 * 128 + 255) / 256, 256>>>(W2, w2h, w2l, 128, 8 * 256 * 128);
    convw_kernel<<<(256 * 128 + 255) / 256, 256>>>(root2, r2h, r2l, 128, 256 * 128);
    split_kernel<<<(int)(((size_t)N * 256 + 255) / 256), 256>>>(x, xh, xl, (size_t)N * 256);

    const int mtiles = (N + 127) / 128;

    // ---- layer 1 ----
    gemm_pipe<__half><<<dim3(mtiles, 16), 256, SMEMP>>>(xh, xl, N, w1h, w1l, nullptr, Y1, 2048);
    gemm_pipe<float> <<<dim3(mtiles, 2),  256, SMEMP>>>(xh, xl, N, r1h, r1l, b1, H, 256);
    gather1_kernel<<<N, 128>>>(Y1, csr, offs, cnt, H, hh, hl);

    // ---- layer 2 ----
    gemm_pipe<__half><<<dim3(mtiles, 8), 256, SMEMP>>>(hh, hl, N, w2h, w2l, nullptr, Y2, 1024);
    gemm_pipe<float> <<<dim3(mtiles, 1), 256, SMEMP>>>(hh, hl, N, r2h, r2l, b2, out, 128);
    gather2_kernel<<<N, 64>>>(Y2, csr, offs, cnt, out);
}